// round 3
// baseline (speedup 1.0000x reference)
#include <cuda_runtime.h>
#include <cstdint>

// Decoder fused kernel: out[b,d] = (x[b,d] - diag_t[b,d]) * exp(-diag_s[b,d])
// diag_p[b,d] = column d of MLP_p(z[b,d,:]);  z[b,d,l] = koopman[b,l,d].
// B=2048, D=64, L=64, H=512.
//
// R1: prep kernels pre-round weights to tf32 AND reshuffle into an
// mma-fragment-major blob (float4 per thread per 2 n-tiles) in __device__
// scratch. Main kernel: 512 threads (2M x 8N warps), inner loop has zero CVT,
// vectorized B loads.

namespace {

constexpr int Hn = 512;
constexpr int LDA = 516;      // activation smem stride (floats)
constexpr int CK = 16;        // K rows per weight chunk
constexpr int CHUNK_F = CK * Hn;  // 8192 floats per chunk blob
constexpr int NTHREADS = 512; // 16 warps: 2 (M) x 8 (N)

// blob offsets (floats): mlp0 L1,L2,L3 then mlp1 L1,L2,L3
__device__ float g_wblob[1114112];
__constant__ int c_blob_off[6] = {0, 32768, 294912, 557056, 589824, 851968};

// dynamic smem (floats)
constexpr int SMEM_A_F    = 64 * LDA;        // 33024
constexpr int SMEM_W_F    = 2 * CHUNK_F;     // 16384
constexpr int SMEM_BIAS_F = Hn;              // 512
constexpr int SMEM_RED_F  = 512;
constexpr int SMEM_S_F    = 64;
constexpr int SMEM_BYTES = (SMEM_A_F + SMEM_W_F + SMEM_BIAS_F + SMEM_RED_F + SMEM_S_F) * 4;

__device__ __forceinline__ float tf32r(float f) {
    asm("cvt.rna.tf32.f32 %0, %0;" : "+f"(f));
    return f;
}
__device__ __forceinline__ void mma8(float c[4], const unsigned a[4], unsigned b0, unsigned b1) {
    asm volatile(
        "mma.sync.aligned.m16n8k8.row.col.f32.tf32.tf32.f32 "
        "{%0,%1,%2,%3}, {%4,%5,%6,%7}, {%8,%9}, {%0,%1,%2,%3};"
        : "+f"(c[0]), "+f"(c[1]), "+f"(c[2]), "+f"(c[3])
        : "r"(a[0]), "r"(a[1]), "r"(a[2]), "r"(a[3]), "r"(b0), "r"(b1));
}
__device__ __forceinline__ void cp16(void* smem_dst, const void* gsrc) {
    unsigned s = (unsigned)__cvta_generic_to_shared(smem_dst);
    asm volatile("cp.async.cg.shared.global [%0], [%1], 16;" :: "r"(s), "l"(gsrc));
}
__device__ __forceinline__ void cp_commit() { asm volatile("cp.async.commit_group;"); }
template <int N>
__device__ __forceinline__ void cp_wait() { asm volatile("cp.async.wait_group %0;" :: "n"(N)); }

__device__ __forceinline__ float fast_tanh(float x) {
    float e = __expf(2.0f * x);
    return 1.0f - __fdividef(2.0f, e + 1.0f);
}

// ---------- prep: W[K,512] fp32 -> tf32 fragment blob ----------
// blob element e (within layer): q=e&3, lane=(e>>2)&31, n2=(e>>7)&3,
// wn=(e>>9)&7, s=(e>>12)&1, c=e>>13.
// k = c*16 + s*8 + (lane&3) + (q&1)*4 ; col = wn*64 + (2*n2+(q>>1))*8 + (lane>>2)
__global__ void prep_kernel(const float* __restrict__ W, int slot, int total) {
    int e = blockIdx.x * blockDim.x + threadIdx.x;
    if (e >= total) return;
    const int q = e & 3;
    const int lane = (e >> 2) & 31;
    const int n2 = (e >> 7) & 3;
    const int wn = (e >> 9) & 7;
    const int s = (e >> 12) & 1;
    const int c = e >> 13;
    const int k = c * 16 + s * 8 + (lane & 3) + (q & 1) * 4;
    const int col = wn * 64 + (2 * n2 + (q >> 1)) * 8 + (lane >> 2);
    g_wblob[c_blob_off[slot] + e] = tf32r(W[k * Hn + col]);
}

// ---------- main ----------
__device__ __forceinline__ void load_chunk(const float* __restrict__ Wg, float* dst,
                                           int c, int tid) {
    const float4* src = reinterpret_cast<const float4*>(Wg + (size_t)c * CHUNK_F);
#pragma unroll
    for (int j = 0; j < (CHUNK_F / 4) / NTHREADS; ++j) {  // 4
        int f4 = tid + j * NTHREADS;
        cp16(dst + f4 * 4, src + f4);
    }
}

template <int K>
__device__ __forceinline__ void gemm_layer(const float* __restrict__ Wg,
                                           const float* __restrict__ bias,
                                           float* sA, float* sW, float* sBias,
                                           float acc[2][8][4],
                                           int tid, int lane, int wm, int wn) {
    constexpr int NCH = K / CK;
#pragma unroll
    for (int m = 0; m < 2; ++m)
#pragma unroll
        for (int n = 0; n < 8; ++n)
#pragma unroll
            for (int q = 0; q < 4; ++q) acc[m][n][q] = 0.0f;

    if (tid < Hn) sBias[tid] = bias[tid];

    load_chunk(Wg, sW, 0, tid);
    cp_commit();

    const int g = lane >> 2;
    const int t4 = lane & 3;

#pragma unroll 1
    for (int c = 0; c < NCH; ++c) {
        if (c + 1 < NCH) {
            load_chunk(Wg, sW + ((c + 1) & 1) * CHUNK_F, c + 1, tid);
            cp_commit();
            cp_wait<1>();
        } else {
            cp_wait<0>();
        }
        __syncthreads();
        const float* wb = sW + (c & 1) * CHUNK_F;
#pragma unroll
        for (int s = 0; s < 2; ++s) {
            const int kk = c * CK + s * 8;
            unsigned a[2][4];
#pragma unroll
            for (int m = 0; m < 2; ++m) {
                const int row = wm * 32 + m * 16 + g;
                const float* ap = sA + row * LDA + kk + t4;
                const float* ap8 = ap + 8 * LDA;
                a[m][0] = __float_as_uint(ap[0]);
                a[m][1] = __float_as_uint(ap8[0]);
                a[m][2] = __float_as_uint(ap[4]);
                a[m][3] = __float_as_uint(ap8[4]);
            }
            const float4* bp = reinterpret_cast<const float4*>(
                                   wb + (size_t)((s * 8 + wn) * 4) * 128) + lane;
#pragma unroll
            for (int n2 = 0; n2 < 4; ++n2) {
                const float4 bv = bp[n2 * 32];
                const unsigned b0 = __float_as_uint(bv.x);
                const unsigned b1 = __float_as_uint(bv.y);
                const unsigned b2 = __float_as_uint(bv.z);
                const unsigned b3 = __float_as_uint(bv.w);
                mma8(acc[0][2 * n2], a[0], b0, b1);
                mma8(acc[1][2 * n2], a[1], b0, b1);
                mma8(acc[0][2 * n2 + 1], a[0], b2, b3);
                mma8(acc[1][2 * n2 + 1], a[1], b2, b3);
            }
        }
        __syncthreads();
    }
}

__device__ __forceinline__ void store_h(const float acc[2][8][4], float* sA,
                                        const float* sBias, int lane, int wm, int wn) {
    const int g = lane >> 2;
    const int t4 = lane & 3;
#pragma unroll
    for (int m = 0; m < 2; ++m) {
        const int row0 = wm * 32 + m * 16 + g;
#pragma unroll
        for (int n = 0; n < 8; ++n) {
            const int col = wn * 64 + n * 8 + t4 * 2;
            const float b0 = sBias[col], b1 = sBias[col + 1];
            sA[row0 * LDA + col]           = tf32r(fast_tanh(acc[m][n][0] + b0));
            sA[row0 * LDA + col + 1]       = tf32r(fast_tanh(acc[m][n][1] + b1));
            sA[(row0 + 8) * LDA + col]     = tf32r(fast_tanh(acc[m][n][2] + b0));
            sA[(row0 + 8) * LDA + col + 1] = tf32r(fast_tanh(acc[m][n][3] + b1));
        }
    }
}

__global__ __launch_bounds__(NTHREADS, 1)
void decoder_kernel(const float* __restrict__ x, const float* __restrict__ koop,
                    const float* __restrict__ sb1, const float* __restrict__ sb2,
                    const float* __restrict__ sb3,
                    const float* __restrict__ sW4, const float* __restrict__ sb4,
                    const float* __restrict__ tb1, const float* __restrict__ tb2,
                    const float* __restrict__ tb3,
                    const float* __restrict__ tW4, const float* __restrict__ tb4,
                    float* __restrict__ out) {
    extern __shared__ float smem[];
    float* sA = smem;
    float* sW = sA + SMEM_A_F;
    float* sBias = sW + SMEM_W_F;
    float* sRed = sBias + SMEM_BIAS_F;
    float* sS = sRed + SMEM_RED_F;

    const int tid = threadIdx.x;
    const int lane = tid & 31;
    const int wid = tid >> 5;
    const int wm = wid >> 3;  // 0..1
    const int wn = wid & 7;   // 0..7
    const int b = blockIdx.x;

    float acc[2][8][4];

#pragma unroll 1
    for (int mlp = 0; mlp < 2; ++mlp) {
        const float* W1 = g_wblob + c_blob_off[mlp * 3 + 0];
        const float* W2 = g_wblob + c_blob_off[mlp * 3 + 1];
        const float* W3 = g_wblob + c_blob_off[mlp * 3 + 2];
        const float* b1 = mlp ? tb1 : sb1;
        const float* b2 = mlp ? tb2 : sb2;
        const float* b3 = mlp ? tb3 : sb3;
        const float* W4 = mlp ? tW4 : sW4;
        const float* b4 = mlp ? tb4 : sb4;

        // z load: sA[d][l] = koopman[b, l, d]
        const float* kb = koop + (size_t)b * 4096;
        for (int i = tid; i < 4096; i += NTHREADS) {
            const int l = i >> 6, d = i & 63;
            sA[d * LDA + l] = tf32r(kb[i]);
        }
        // first __syncthreads inside gemm_layer covers visibility

        gemm_layer<64>(W1, b1, sA, sW, sBias, acc, tid, lane, wm, wn);
        store_h(acc, sA, sBias, lane, wm, wn);
        __syncthreads();
        gemm_layer<512>(W2, b2, sA, sW, sBias, acc, tid, lane, wm, wn);
        store_h(acc, sA, sBias, lane, wm, wn);
        __syncthreads();
        gemm_layer<512>(W3, b3, sA, sW, sBias, acc, tid, lane, wm, wn);
        store_h(acc, sA, sBias, lane, wm, wn);
        __syncthreads();

        // layer 4 diagonal: row r dots W4[:, r]; 8 partials per row
        const int r = tid & 63;
        const int p = tid >> 6;  // 0..7
        float a4 = 0.0f;
        const float* hrow = sA + r * LDA + p * 64;
        const float* wcol = W4 + (size_t)(p * 64) * 64 + r;
#pragma unroll 8
        for (int i = 0; i < 64; ++i)
            a4 += hrow[i] * __ldg(wcol + (size_t)i * 64);
        sRed[p * 64 + r] = a4;
        __syncthreads();
        if (tid < 64) {
            float v = b4[tid];
#pragma unroll
            for (int p2 = 0; p2 < 8; ++p2) v += sRed[p2 * 64 + tid];
            if (mlp == 0) {
                sS[tid] = v;
            } else {
                const size_t o = (size_t)b * 64 + tid;
                out[o] = (x[o] - v) * __expf(-sS[tid]);
            }
        }
        __syncthreads();
    }
}

}  // namespace

extern "C" void kernel_launch(void* const* d_in, const int* in_sizes, int n_in,
                              void* d_out, int out_size) {
    (void)in_sizes; (void)n_in; (void)out_size;
    const float* x    = (const float*)d_in[0];
    const float* koop = (const float*)d_in[1];
    const float* sW1 = (const float*)d_in[2];
    const float* sb1 = (const float*)d_in[3];
    const float* sW2 = (const float*)d_in[4];
    const float* sb2 = (const float*)d_in[5];
    const float* sW3 = (const float*)d_in[6];
    const float* sb3 = (const float*)d_in[7];
    const float* sW4 = (const float*)d_in[8];
    const float* sb4 = (const float*)d_in[9];
    const float* tW1 = (const float*)d_in[10];
    const float* tb1 = (const float*)d_in[11];
    const float* tW2 = (const float*)d_in[12];
    const float* tb2 = (const float*)d_in[13];
    const float* tW3 = (const float*)d_in[14];
    const float* tb3 = (const float*)d_in[15];
    const float* tW4 = (const float*)d_in[16];
    const float* tb4 = (const float*)d_in[17];
    float* out = (float*)d_out;

    // prep: tf32-round + fragment-shuffle the 6 hidden-layer weight matrices
    const float* srcs[6] = {sW1, sW2, sW3, tW1, tW2, tW3};
    const int sizes[6] = {32768, 262144, 262144, 32768, 262144, 262144};
    for (int i = 0; i < 6; ++i)
        prep_kernel<<<(sizes[i] + 255) / 256, 256>>>(srcs[i], i, sizes[i]);

    cudaFuncSetAttribute(decoder_kernel, cudaFuncAttributeMaxDynamicSharedMemorySize,
                         SMEM_BYTES);
    decoder_kernel<<<2048, NTHREADS, SMEM_BYTES>>>(
        x, koop, sb1, sb2, sb3, sW4, sb4,
        tb1, tb2, tb3, tW4, tb4, out);
}

// round 6
// speedup vs baseline: 1.6813x; 1.6813x over previous
#include <cuda_runtime.h>
#include <cuda_fp16.h>
#include <cstdint>

// Decoder: out[b,d] = (x[b,d] - diag_t[b,d]) * exp(-diag_s[b,d])
// Legacy-mma fp16 version (tcgen05 unavailable: harness targets plain sm_103).
// One CTA per batch (M=64). HMMA m16n8k16 f16f32, 16 warps (2M x 8N).
// Weights pre-converted to fp16 fragment-major blob; B frags load as LDS.128.

namespace {

constexpr int Hn = 512;
constexpr int LDA = 520;        // A stride in halves (1040B, 260 words = 4 mod 32)
constexpr int NTHREADS = 512;   // 16 warps: 2(M) x 8(N)
constexpr int CHUNK_U32 = 4096; // 16k x 512n fp16 = 16KB per chunk

// blob (u32 = f16x2): mlp0 L1,L2,L3 then mlp1
__device__ uint32_t g_wblob[557056];
__constant__ int c_blob_off[6] = {0, 16384, 147456, 278528, 294912, 425984};

// smem byte offsets
constexpr int OFF_A = 0;          // 66560 B : A tile 64 x LDA halves
constexpr int OFF_W = 66560;      // 32768 B : 2 x 16KB chunk double buffer
constexpr int OFF_BIAS = 99328;   // 2048 B  : 512 f32
constexpr int OFF_RED = 101376;   // 2048 B  : 512 f32
constexpr int OFF_S = 103424;     // 256 B   : 64 f32
constexpr int SMEM_BYTES = 103680;

__device__ __forceinline__ void mma16(float c[4], const unsigned a[4],
                                      unsigned b0, unsigned b1) {
    asm volatile(
        "mma.sync.aligned.m16n8k16.row.col.f32.f16.f16.f32 "
        "{%0,%1,%2,%3}, {%4,%5,%6,%7}, {%8,%9}, {%0,%1,%2,%3};"
        : "+f"(c[0]), "+f"(c[1]), "+f"(c[2]), "+f"(c[3])
        : "r"(a[0]), "r"(a[1]), "r"(a[2]), "r"(a[3]), "r"(b0), "r"(b1));
}
__device__ __forceinline__ void cp16(void* smem_dst, const void* gsrc) {
    unsigned s = (unsigned)__cvta_generic_to_shared(smem_dst);
    asm volatile("cp.async.cg.shared.global [%0], [%1], 16;" :: "r"(s), "l"(gsrc));
}
__device__ __forceinline__ void cp_commit() { asm volatile("cp.async.commit_group;"); }
template <int N>
__device__ __forceinline__ void cp_wait() { asm volatile("cp.async.wait_group %0;" :: "n"(N)); }

__device__ __forceinline__ float fast_tanh(float x) {
    float e = __expf(2.0f * x);
    return 1.0f - __fdividef(2.0f, e + 1.0f);
}
// pack two f32 -> f16x2, lo = first arg
__device__ __forceinline__ uint32_t pack_f16x2(float lo, float hi) {
    uint32_t r;
    asm("cvt.rn.f16x2.f32 %0, %1, %2;" : "=r"(r) : "f"(hi), "f"(lo));
    return r;
}

// ---- prep: W[K,512] fp32 -> fp16 fragment-major blob ----
// u32 element e: q=e&3, lane=(e>>2)&31, p=(e>>7)&3, wn=(e>>9)&7, chunk=e>>12
// k = chunk*16 + 2*(lane&3) + 8*(q&1);  col = wn*64 + (2p + (q>>1))*8 + (lane>>2)
// value = f16x2( W[k][col], W[k+1][col] )
__global__ void prep_kernel(const float* __restrict__ W, int base_u32, int total_u32) {
    int e = blockIdx.x * blockDim.x + threadIdx.x;
    if (e >= total_u32) return;
    const int q = e & 3;
    const int lane = (e >> 2) & 31;
    const int p = (e >> 7) & 3;
    const int wn = (e >> 9) & 7;
    const int chunk = e >> 12;
    const int k = chunk * 16 + 2 * (lane & 3) + 8 * (q & 1);
    const int col = wn * 64 + (2 * p + (q >> 1)) * 8 + (lane >> 2);
    g_wblob[base_u32 + e] = pack_f16x2(W[k * Hn + col], W[(k + 1) * Hn + col]);
}

// ---- main ----
__device__ __forceinline__ void load_chunk(const uint32_t* __restrict__ Wg,
                                           uint32_t* dst, int c, int tid) {
    const char* src = (const char*)(Wg + (size_t)c * CHUNK_U32);
#pragma unroll
    for (int j = 0; j < 2; ++j) {
        int f4 = tid + j * NTHREADS;     // 0..1023 (16B units)
        cp16((char*)dst + f4 * 16, src + f4 * 16);
    }
}

template <int K>
__device__ __forceinline__ void gemm_layer(const uint32_t* __restrict__ Wg,
                                           const float* __restrict__ bias,
                                           __half* sA, uint32_t* sW, float* sBias,
                                           float acc[2][8][4],
                                           int tid, int lane, int wm, int wn) {
    constexpr int NCH = K / 16;
#pragma unroll
    for (int m = 0; m < 2; ++m)
#pragma unroll
        for (int n = 0; n < 8; ++n)
#pragma unroll
            for (int q = 0; q < 4; ++q) acc[m][n][q] = 0.0f;

    sBias[tid] = bias[tid];

    load_chunk(Wg, sW, 0, tid);
    cp_commit();

    const int g = lane >> 2;
    const int t4 = lane & 3;

#pragma unroll 1
    for (int c = 0; c < NCH; ++c) {
        if (c + 1 < NCH) {
            load_chunk(Wg, sW + ((c + 1) & 1) * CHUNK_U32, c + 1, tid);
            cp_commit();
            cp_wait<1>();
        } else {
            cp_wait<0>();
        }
        __syncthreads();

        unsigned a[2][4];
#pragma unroll
        for (int m = 0; m < 2; ++m) {
            const __half* ap = sA + (wm * 32 + m * 16 + g) * LDA + c * 16 + 2 * t4;
            a[m][0] = *(const uint32_t*)ap;
            a[m][1] = *(const uint32_t*)(ap + 8 * LDA);
            a[m][2] = *(const uint32_t*)(ap + 8);
            a[m][3] = *(const uint32_t*)(ap + 8 * LDA + 8);
        }
        const uint4* wb = (const uint4*)(sW + (c & 1) * CHUNK_U32) + wn * 128 + lane;
#pragma unroll
        for (int p = 0; p < 4; ++p) {
            const uint4 bv = wb[p * 32];
            mma16(acc[0][2 * p],     a[0], bv.x, bv.y);
            mma16(acc[1][2 * p],     a[1], bv.x, bv.y);
            mma16(acc[0][2 * p + 1], a[0], bv.z, bv.w);
            mma16(acc[1][2 * p + 1], a[1], bv.z, bv.w);
        }
        __syncthreads();
    }
}

__device__ __forceinline__ void store_h(const float acc[2][8][4], __half* sA,
                                        const float* sBias, int lane, int wm, int wn) {
    const int g = lane >> 2;
    const int t4 = lane & 3;
#pragma unroll
    for (int m = 0; m < 2; ++m) {
        const int row0 = wm * 32 + m * 16 + g;
#pragma unroll
        for (int n = 0; n < 8; ++n) {
            const int col = wn * 64 + n * 8 + 2 * t4;
            const float b0 = sBias[col], b1 = sBias[col + 1];
            *(uint32_t*)(sA + row0 * LDA + col) =
                pack_f16x2(fast_tanh(acc[m][n][0] + b0), fast_tanh(acc[m][n][1] + b1));
            *(uint32_t*)(sA + (row0 + 8) * LDA + col) =
                pack_f16x2(fast_tanh(acc[m][n][2] + b0), fast_tanh(acc[m][n][3] + b1));
        }
    }
}

__global__ __launch_bounds__(NTHREADS, 1)
void decoder_kernel(const float* __restrict__ x, const float* __restrict__ koop,
                    const float* __restrict__ sb1, const float* __restrict__ sb2,
                    const float* __restrict__ sb3,
                    const float* __restrict__ sW4, const float* __restrict__ sb4,
                    const float* __restrict__ tb1, const float* __restrict__ tb2,
                    const float* __restrict__ tb3,
                    const float* __restrict__ tW4, const float* __restrict__ tb4,
                    float* __restrict__ out) {
    extern __shared__ char smem[];
    __half* sA = (__half*)(smem + OFF_A);
    uint32_t* sW = (uint32_t*)(smem + OFF_W);
    float* sBias = (float*)(smem + OFF_BIAS);
    float* sRed = (float*)(smem + OFF_RED);
    float* sS = (float*)(smem + OFF_S);

    const int tid = threadIdx.x;
    const int lane = tid & 31;
    const int wid = tid >> 5;
    const int wm = wid >> 3;  // 0..1
    const int wn = wid & 7;   // 0..7
    const int b = blockIdx.x;

    float acc[2][8][4];

#pragma unroll 1
    for (int mlp = 0; mlp < 2; ++mlp) {
        const uint32_t* W1 = g_wblob + c_blob_off[mlp * 3 + 0];
        const uint32_t* W2 = g_wblob + c_blob_off[mlp * 3 + 1];
        const uint32_t* W3 = g_wblob + c_blob_off[mlp * 3 + 2];
        const float* b1 = mlp ? tb1 : sb1;
        const float* b2 = mlp ? tb2 : sb2;
        const float* b3 = mlp ? tb3 : sb3;
        const float* W4 = mlp ? tW4 : sW4;
        const float* b4 = mlp ? tb4 : sb4;

        // z load: sA[d][l] = koopman[b, l, d] as f16
        const float* kb = koop + (size_t)b * 4096;
        for (int i = tid; i < 4096; i += NTHREADS) {
            const int l = i >> 6, d = i & 63;
            sA[d * LDA + l] = __float2half_rn(kb[i]);
        }
        // visibility covered by gemm_layer's first __syncthreads before A reads

        gemm_layer<64>(W1, b1, sA, sW, sBias, acc, tid, lane, wm, wn);
        store_h(acc, sA, sBias, lane, wm, wn);
        __syncthreads();
        gemm_layer<512>(W2, b2, sA, sW, sBias, acc, tid, lane, wm, wn);
        store_h(acc, sA, sBias, lane, wm, wn);
        __syncthreads();
        gemm_layer<512>(W3, b3, sA, sW, sBias, acc, tid, lane, wm, wn);
        store_h(acc, sA, sBias, lane, wm, wn);
        __syncthreads();

        // layer 4 diagonal: row r dots W4[:, r]; 8 partials per row
        const int r = tid & 63;
        const int p = tid >> 6;  // 0..7
        float a4 = 0.0f;
        const __half* hrow = sA + r * LDA + p * 64;
        const float* wcol = W4 + (size_t)(p * 64) * 64 + r;
#pragma unroll 8
        for (int i = 0; i < 64; ++i)
            a4 += __half2float(hrow[i]) * __ldg(wcol + (size_t)i * 64);
        sRed[p * 64 + r] = a4;
        __syncthreads();
        if (tid < 64) {
            float v = b4[tid];
#pragma unroll
            for (int p2 = 0; p2 < 8; ++p2) v += sRed[p2 * 64 + tid];
            if (mlp == 0) {
                sS[tid] = v;
            } else {
                const size_t o = (size_t)b * 64 + tid;
                out[o] = (x[o] - v) * __expf(-sS[tid]);
            }
        }
        __syncthreads();
    }
}

}  // namespace

extern "C" void kernel_launch(void* const* d_in, const int* in_sizes, int n_in,
                              void* d_out, int out_size) {
    (void)in_sizes; (void)n_in; (void)out_size;
    const float* x    = (const float*)d_in[0];
    const float* koop = (const float*)d_in[1];
    const float* sW1 = (const float*)d_in[2];  const float* sb1 = (const float*)d_in[3];
    const float* sW2 = (const float*)d_in[4];  const float* sb2 = (const float*)d_in[5];
    const float* sW3 = (const float*)d_in[6];  const float* sb3 = (const float*)d_in[7];
    const float* sW4 = (const float*)d_in[8];  const float* sb4 = (const float*)d_in[9];
    const float* tW1 = (const float*)d_in[10]; const float* tb1 = (const float*)d_in[11];
    const float* tW2 = (const float*)d_in[12]; const float* tb2 = (const float*)d_in[13];
    const float* tW3 = (const float*)d_in[14]; const float* tb3 = (const float*)d_in[15];
    const float* tW4 = (const float*)d_in[16]; const float* tb4 = (const float*)d_in[17];
    float* out = (float*)d_out;

    // prep: fp16-convert + fragment-shuffle hidden-layer weights (u32 counts)
    const float* srcs[6] = {sW1, sW2, sW3, tW1, tW2, tW3};
    const int bases[6] = {0, 16384, 147456, 278528, 294912, 425984};
    const int tots[6] = {16384, 131072, 131072, 16384, 131072, 131072};
    for (int i = 0; i < 6; ++i)
        prep_kernel<<<(tots[i] + 255) / 256, 256>>>(srcs[i], bases[i], tots[i]);

    cudaFuncSetAttribute(decoder_kernel, cudaFuncAttributeMaxDynamicSharedMemorySize,
                         SMEM_BYTES);
    decoder_kernel<<<2048, NTHREADS, SMEM_BYTES>>>(
        x, koop, sb1, sb2, sb3, sW4, sb4,
        tb1, tb2, tb3, tW4, tb4, out);
}

// round 7
// speedup vs baseline: 1.7363x; 1.0327x over previous
#include <cuda_runtime.h>
#include <cuda_fp16.h>
#include <cstdint>

// Decoder: out[b,d] = (x[b,d] - diag_t[b,d]) * exp(-diag_s[b,d])
// fp16 HMMA m16n8k16, one CTA per batch (M=64), 16 warps (2M x 8N).
// R6: 32-k super-chunks, 3-slot ring, ONE barrier per chunk, prefetch depth 2.

namespace {

constexpr int Hn = 512;
constexpr int LDA = 520;          // A stride in halves
constexpr int NTHREADS = 512;     // 16 warps: 2(M) x 8(N)
constexpr int SUPER_U32 = 8192;   // 32k x 512n fp16 = 32KB per super-chunk

// blob (u32 = f16x2), fragment-major in 16-k chunks: mlp0 L1,L2,L3 then mlp1
__device__ uint32_t g_wblob[557056];
__constant__ int c_blob_off[7] = {0, 16384, 147456, 278528, 294912, 425984, 557056};

// smem byte offsets
constexpr int OFF_A = 0;            // 66560 B : A tile 64 x LDA halves
constexpr int OFF_W = 66560;        // 98304 B : 3 x 32KB ring
constexpr int OFF_BIAS = 164864;    // 2048 B
constexpr int OFF_RED = 166912;     // 2048 B
constexpr int OFF_S = 168960;       // 256 B
constexpr int SMEM_BYTES = 169216;

__device__ __forceinline__ void mma16(float c[4], const unsigned a[4],
                                      unsigned b0, unsigned b1) {
    asm volatile(
        "mma.sync.aligned.m16n8k16.row.col.f32.f16.f16.f32 "
        "{%0,%1,%2,%3}, {%4,%5,%6,%7}, {%8,%9}, {%0,%1,%2,%3};"
        : "+f"(c[0]), "+f"(c[1]), "+f"(c[2]), "+f"(c[3])
        : "r"(a[0]), "r"(a[1]), "r"(a[2]), "r"(a[3]), "r"(b0), "r"(b1));
}
__device__ __forceinline__ void cp16(void* smem_dst, const void* gsrc) {
    unsigned s = (unsigned)__cvta_generic_to_shared(smem_dst);
    asm volatile("cp.async.cg.shared.global [%0], [%1], 16;" :: "r"(s), "l"(gsrc));
}
__device__ __forceinline__ void cp_commit() { asm volatile("cp.async.commit_group;"); }
template <int N>
__device__ __forceinline__ void cp_wait() { asm volatile("cp.async.wait_group %0;" :: "n"(N)); }

__device__ __forceinline__ float fast_tanh(float x) {
    float e = __expf(2.0f * x);
    return 1.0f - __fdividef(2.0f, e + 1.0f);
}
__device__ __forceinline__ uint32_t pack_f16x2(float lo, float hi) {
    uint32_t r;
    asm("cvt.rn.f16x2.f32 %0, %1, %2;" : "=r"(r) : "f"(hi), "f"(lo));
    return r;
}

// ---- fused prep: all 6 hidden-layer weights -> fp16 fragment blob ----
// within a layer, u32 element e: q=e&3, lane=(e>>2)&31, p=(e>>7)&3, wn=(e>>9)&7,
// chunk=e>>12 (16-k chunks).
// k = chunk*16 + 2*(lane&3) + 8*(q&1);  col = wn*64 + (2p+(q>>1))*8 + (lane>>2)
__global__ void prep_kernel(const float* __restrict__ W0, const float* __restrict__ W1,
                            const float* __restrict__ W2, const float* __restrict__ W3,
                            const float* __restrict__ W4, const float* __restrict__ W5) {
    const int eg = blockIdx.x * blockDim.x + threadIdx.x;
    if (eg >= 557056) return;
    const float* srcs[6] = {W0, W1, W2, W3, W4, W5};
    int slot = 0;
    while (eg >= c_blob_off[slot + 1]) ++slot;
    const float* W = srcs[slot];
    const int e = eg - c_blob_off[slot];
    const int q = e & 3;
    const int lane = (e >> 2) & 31;
    const int p = (e >> 7) & 3;
    const int wn = (e >> 9) & 7;
    const int chunk = e >> 12;
    const int k = chunk * 16 + 2 * (lane & 3) + 8 * (q & 1);
    const int col = wn * 64 + (2 * p + (q >> 1)) * 8 + (lane >> 2);
    g_wblob[eg] = pack_f16x2(W[k * Hn + col], W[(k + 1) * Hn + col]);
}

// ---- main ----
__device__ __forceinline__ void load_super(const uint32_t* __restrict__ Wg,
                                           char* ringbase, int c, int tid) {
    const char* src = (const char*)(Wg + (size_t)c * SUPER_U32);
    char* dst = ringbase + (c % 3) * 32768;
#pragma unroll
    for (int j = 0; j < 4; ++j) {
        const int f4 = tid + j * NTHREADS;   // 0..2047 (16B units)
        cp16(dst + f4 * 16, src + f4 * 16);
    }
    cp_commit();
}

template <int NCH>
__device__ __forceinline__ void gemm_layer(const uint32_t* __restrict__ Wg,
                                           const float* __restrict__ bias,
                                           __half* sA, char* ring, float* sBias,
                                           float acc[2][8][4],
                                           int tid, int lane, int wm, int wn) {
#pragma unroll
    for (int m = 0; m < 2; ++m)
#pragma unroll
        for (int n = 0; n < 8; ++n)
#pragma unroll
            for (int q = 0; q < 4; ++q) acc[m][n][q] = 0.0f;

    sBias[tid] = bias[tid];

    load_super(Wg, ring, 0, tid);
    if (NCH > 1) load_super(Wg, ring, 1, tid);

    const int g = lane >> 2;
    const int t4 = lane & 3;

#pragma unroll 1
    for (int c = 0; c < NCH; ++c) {
        if (c + 1 < NCH) cp_wait<1>(); else cp_wait<0>();
        __syncthreads();   // chunk c visible to all; slot (c+2)%3 (= c-1) drained
        if (c + 2 < NCH) load_super(Wg, ring, c + 2, tid);

        const uint32_t* wb = (const uint32_t*)(ring + (c % 3) * 32768);
#pragma unroll
        for (int kh = 0; kh < 2; ++kh) {
            unsigned a[2][4];
#pragma unroll
            for (int m = 0; m < 2; ++m) {
                const __half* ap = sA + (wm * 32 + m * 16 + g) * LDA
                                 + c * 32 + kh * 16 + 2 * t4;
                a[m][0] = *(const uint32_t*)ap;
                a[m][1] = *(const uint32_t*)(ap + 8 * LDA);
                a[m][2] = *(const uint32_t*)(ap + 8);
                a[m][3] = *(const uint32_t*)(ap + 8 * LDA + 8);
            }
            const uint4* bp = (const uint4*)(wb + kh * 4096) + wn * 128 + lane;
#pragma unroll
            for (int p = 0; p < 4; ++p) {
                const uint4 bv = bp[p * 32];
                mma16(acc[0][2 * p],     a[0], bv.x, bv.y);
                mma16(acc[1][2 * p],     a[1], bv.x, bv.y);
                mma16(acc[0][2 * p + 1], a[0], bv.z, bv.w);
                mma16(acc[1][2 * p + 1], a[1], bv.z, bv.w);
            }
        }
    }
    __syncthreads();   // last chunk's reads done before sA overwritten by store_h
}

__device__ __forceinline__ void store_h(const float acc[2][8][4], __half* sA,
                                        const float* sBias, int lane, int wm, int wn) {
    const int g = lane >> 2;
    const int t4 = lane & 3;
#pragma unroll
    for (int m = 0; m < 2; ++m) {
        const int row0 = wm * 32 + m * 16 + g;
#pragma unroll
        for (int n = 0; n < 8; ++n) {
            const int col = wn * 64 + n * 8 + 2 * t4;
            const float b0 = sBias[col], b1 = sBias[col + 1];
            *(uint32_t*)(sA + row0 * LDA + col) =
                pack_f16x2(fast_tanh(acc[m][n][0] + b0), fast_tanh(acc[m][n][1] + b1));
            *(uint32_t*)(sA + (row0 + 8) * LDA + col) =
                pack_f16x2(fast_tanh(acc[m][n][2] + b0), fast_tanh(acc[m][n][3] + b1));
        }
    }
}

__global__ __launch_bounds__(NTHREADS, 1)
void decoder_kernel(const float* __restrict__ x, const float* __restrict__ koop,
                    const float* __restrict__ sb1, const float* __restrict__ sb2,
                    const float* __restrict__ sb3,
                    const float* __restrict__ sW4, const float* __restrict__ sb4,
                    const float* __restrict__ tb1, const float* __restrict__ tb2,
                    const float* __restrict__ tb3,
                    const float* __restrict__ tW4, const float* __restrict__ tb4,
                    float* __restrict__ out) {
    extern __shared__ char smem[];
    __half* sA = (__half*)(smem + OFF_A);
    char* ring = smem + OFF_W;
    float* sBias = (float*)(smem + OFF_BIAS);
    float* sRed = (float*)(smem + OFF_RED);
    float* sS = (float*)(smem + OFF_S);

    const int tid = threadIdx.x;
    const int lane = tid & 31;
    const int wid = tid >> 5;
    const int wm = wid >> 3;   // 0..1
    const int wn = wid & 7;    // 0..7
    const int b = blockIdx.x;

    float acc[2][8][4];

#pragma unroll 1
    for (int mlp = 0; mlp < 2; ++mlp) {
        const uint32_t* W1 = g_wblob + c_blob_off[mlp * 3 + 0];
        const uint32_t* W2 = g_wblob + c_blob_off[mlp * 3 + 1];
        const uint32_t* W3 = g_wblob + c_blob_off[mlp * 3 + 2];
        const float* b1 = mlp ? tb1 : sb1;
        const float* b2 = mlp ? tb2 : sb2;
        const float* b3 = mlp ? tb3 : sb3;
        const float* W4 = mlp ? tW4 : sW4;
        const float* b4 = mlp ? tb4 : sb4;

        // z load: sA[d][l] = koopman[b, l, d] as f16
        const float* kb = koop + (size_t)b * 4096;
        for (int i = tid; i < 4096; i += NTHREADS) {
            const int l = i >> 6, d = i & 63;
            sA[d * LDA + l] = __float2half_rn(kb[i]);
        }
        // visibility: first in-loop __syncthreads of gemm_layer

        gemm_layer<2>(W1, b1, sA, ring, sBias, acc, tid, lane, wm, wn);
        store_h(acc, sA, sBias, lane, wm, wn);
        __syncthreads();
        gemm_layer<16>(W2, b2, sA, ring, sBias, acc, tid, lane, wm, wn);
        store_h(acc, sA, sBias, lane, wm, wn);
        __syncthreads();
        gemm_layer<16>(W3, b3, sA, ring, sBias, acc, tid, lane, wm, wn);
        store_h(acc, sA, sBias, lane, wm, wn);
        __syncthreads();

        // layer 4 diagonal: row r dots W4[:, r]; 8 partials per row
        const int r = tid & 63;
        const int p = tid >> 6;   // 0..7
        float a4 = 0.0f;
        const __half2* hrow = (const __half2*)(sA + r * LDA + p * 64);
        const float* wcol = W4 + (size_t)(p * 64) * 64 + r;
#pragma unroll 8
        for (int i = 0; i < 32; ++i) {
            const float2 hv = __half22float2(hrow[i]);
            a4 += hv.x * __ldg(wcol + (size_t)(2 * i) * 64);
            a4 += hv.y * __ldg(wcol + (size_t)(2 * i + 1) * 64);
        }
        sRed[p * 64 + r] = a4;
        __syncthreads();
        if (tid < 64) {
            float v = b4[tid];
#pragma unroll
            for (int p2 = 0; p2 < 8; ++p2) v += sRed[p2 * 64 + tid];
            if (mlp == 0) {
                sS[tid] = v;
            } else {
                const size_t o = (size_t)b * 64 + tid;
                out[o] = (x[o] - v) * __expf(-sS[tid]);
            }
        }
        __syncthreads();
    }
}

}  // namespace

extern "C" void kernel_launch(void* const* d_in, const int* in_sizes, int n_in,
                              void* d_out, int out_size) {
    (void)in_sizes; (void)n_in; (void)out_size;
    const float* x    = (const float*)d_in[0];
    const float* koop = (const float*)d_in[1];
    const float* sW1 = (const float*)d_in[2];  const float* sb1 = (const float*)d_in[3];
    const float* sW2 = (const float*)d_in[4];  const float* sb2 = (const float*)d_in[5];
    const float* sW3 = (const float*)d_in[6];  const float* sb3 = (const float*)d_in[7];
    const float* sW4 = (const float*)d_in[8];  const float* sb4 = (const float*)d_in[9];
    const float* tW1 = (const float*)d_in[10]; const float* tb1 = (const float*)d_in[11];
    const float* tW2 = (const float*)d_in[12]; const float* tb2 = (const float*)d_in[13];
    const float* tW3 = (const float*)d_in[14]; const float* tb3 = (const float*)d_in[15];
    const float* tW4 = (const float*)d_in[16]; const float* tb4 = (const float*)d_in[17];
    float* out = (float*)d_out;

    prep_kernel<<<(557056 + 255) / 256, 256>>>(sW1, sW2, sW3, tW1, tW2, tW3);

    cudaFuncSetAttribute(decoder_kernel, cudaFuncAttributeMaxDynamicSharedMemorySize,
                         SMEM_BYTES);
    decoder_kernel<<<2048, NTHREADS, SMEM_BYTES>>>(
        x, koop, sb1, sb2, sb3, sW4, sb4,
        tb1, tb2, tb3, tW4, tb4, out);
}

// round 8
// speedup vs baseline: 1.9186x; 1.1050x over previous
#include <cuda_runtime.h>
#include <cuda_fp16.h>
#include <cstdint>

// Decoder: out[b,d] = (x[b,d] - diag_t[b,d]) * exp(-diag_s[b,d])
// fp16 HMMA m16n8k16, one CTA per batch (M=64), 16 warps (2M x 8N).
// R7: explicit software pipeline — ping-pong register fragments (ldmatrix A,
// LDS.128 B) so loads for step s+1 issue before HMMAs of step s.

namespace {

constexpr int Hn = 512;
constexpr int LDA = 520;          // A stride in halves (1040 B)
constexpr int NTHREADS = 512;     // 16 warps: 2(M) x 8(N)
constexpr int SUPER_U32 = 8192;   // 32k x 512n fp16 = 32KB per super-chunk

// blob (u32 = f16x2), fragment-major in 16-k chunks: mlp0 L1,L2,L3 then mlp1
__device__ uint32_t g_wblob[557056];
__constant__ int c_blob_off[7] = {0, 16384, 147456, 278528, 294912, 425984, 557056};

// smem byte offsets
constexpr int OFF_A = 0;            // 66560 B : A tile 64 x LDA halves
constexpr int OFF_W = 66560;        // 98304 B : 3 x 32KB ring
constexpr int OFF_BIAS = 164864;    // 2048 B
constexpr int OFF_RED = 166912;     // 2048 B
constexpr int OFF_S = 168960;       // 256 B
constexpr int SMEM_BYTES = 169216;

__device__ __forceinline__ void mma16(float c[4], const unsigned a[4],
                                      unsigned b0, unsigned b1) {
    asm volatile(
        "mma.sync.aligned.m16n8k16.row.col.f32.f16.f16.f32 "
        "{%0,%1,%2,%3}, {%4,%5,%6,%7}, {%8,%9}, {%0,%1,%2,%3};"
        : "+f"(c[0]), "+f"(c[1]), "+f"(c[2]), "+f"(c[3])
        : "r"(a[0]), "r"(a[1]), "r"(a[2]), "r"(a[3]), "r"(b0), "r"(b1));
}
__device__ __forceinline__ void ldsm4(unsigned r[4], uint32_t addr) {
    asm volatile("ldmatrix.sync.aligned.m8n8.x4.shared.b16 {%0,%1,%2,%3}, [%4];"
                 : "=r"(r[0]), "=r"(r[1]), "=r"(r[2]), "=r"(r[3]) : "r"(addr));
}
__device__ __forceinline__ void cp16(void* smem_dst, const void* gsrc) {
    unsigned s = (unsigned)__cvta_generic_to_shared(smem_dst);
    asm volatile("cp.async.cg.shared.global [%0], [%1], 16;" :: "r"(s), "l"(gsrc));
}
__device__ __forceinline__ void cp_commit() { asm volatile("cp.async.commit_group;"); }
template <int N>
__device__ __forceinline__ void cp_wait() { asm volatile("cp.async.wait_group %0;" :: "n"(N)); }

__device__ __forceinline__ float fast_tanh(float x) {
    float e = __expf(2.0f * x);
    return 1.0f - __fdividef(2.0f, e + 1.0f);
}
__device__ __forceinline__ uint32_t pack_f16x2(float lo, float hi) {
    uint32_t r;
    asm("cvt.rn.f16x2.f32 %0, %1, %2;" : "=r"(r) : "f"(hi), "f"(lo));
    return r;
}

// ---- fused prep: all 6 hidden-layer weights -> fp16 fragment blob ----
__global__ void prep_kernel(const float* __restrict__ W0, const float* __restrict__ W1,
                            const float* __restrict__ W2, const float* __restrict__ W3,
                            const float* __restrict__ W4, const float* __restrict__ W5) {
    const int eg = blockIdx.x * blockDim.x + threadIdx.x;
    if (eg >= 557056) return;
    const float* srcs[6] = {W0, W1, W2, W3, W4, W5};
    int slot = 0;
    while (eg >= c_blob_off[slot + 1]) ++slot;
    const float* W = srcs[slot];
    const int e = eg - c_blob_off[slot];
    const int q = e & 3;
    const int lane = (e >> 2) & 31;
    const int p = (e >> 7) & 3;
    const int wn = (e >> 9) & 7;
    const int chunk = e >> 12;
    const int k = chunk * 16 + 2 * (lane & 3) + 8 * (q & 1);
    const int col = wn * 64 + (2 * p + (q >> 1)) * 8 + (lane >> 2);
    g_wblob[eg] = pack_f16x2(W[k * Hn + col], W[(k + 1) * Hn + col]);
}

// ---- main ----
__device__ __forceinline__ void load_super(const uint32_t* __restrict__ Wg,
                                           char* ringbase, int c, int tid) {
    const char* src = (const char*)(Wg + (size_t)c * SUPER_U32);
    char* dst = ringbase + (c % 3) * 32768;
#pragma unroll
    for (int j = 0; j < 4; ++j) {
        const int f4 = tid + j * NTHREADS;
        cp16(dst + f4 * 16, src + f4 * 16);
    }
    cp_commit();
}

struct Frag {
    unsigned a[2][4];
    uint4 b[4];
};

__device__ __forceinline__ void load_frag(Frag& f, uint32_t aaddr0, uint32_t aaddr1,
                                          const char* bbase, int wn, int lane) {
    ldsm4(f.a[0], aaddr0);
    ldsm4(f.a[1], aaddr1);
    const uint4* bp = (const uint4*)bbase + wn * 128 + lane;
#pragma unroll
    for (int p = 0; p < 4; ++p) f.b[p] = bp[p * 32];
}

__device__ __forceinline__ void do_mma(float acc[2][8][4], const Frag& f) {
#pragma unroll
    for (int p = 0; p < 4; ++p) {
        mma16(acc[0][2 * p],     f.a[0], f.b[p].x, f.b[p].y);
        mma16(acc[1][2 * p],     f.a[1], f.b[p].x, f.b[p].y);
        mma16(acc[0][2 * p + 1], f.a[0], f.b[p].z, f.b[p].w);
        mma16(acc[1][2 * p + 1], f.a[1], f.b[p].z, f.b[p].w);
    }
}

template <int NCH>
__device__ __forceinline__ void gemm_layer(const uint32_t* __restrict__ Wg,
                                           const float* __restrict__ bias,
                                           __half* sA, char* ring, float* sBias,
                                           float acc[2][8][4],
                                           int tid, int lane, int wm, int wn) {
#pragma unroll
    for (int m = 0; m < 2; ++m)
#pragma unroll
        for (int n = 0; n < 8; ++n)
#pragma unroll
            for (int q = 0; q < 4; ++q) acc[m][n][q] = 0.0f;

    sBias[tid] = bias[tid];

    load_super(Wg, ring, 0, tid);
    if (NCH > 1) load_super(Wg, ring, 1, tid);

    // ldmatrix lane addressing: lanes 0-7 rows m..m+7 col k; 8-15 rows m+8..;
    // 16-23 rows m..m+7 col k+8; 24-31 rows m+8.. col k+8.
    const int arow = wm * 32 + (lane & 7) + ((lane >> 3) & 1) * 8;
    const int acol = (lane >> 4) * 8;
    uint32_t aaddr0 = (unsigned)__cvta_generic_to_shared(sA + arow * LDA + acol);
    uint32_t aaddr1 = aaddr0 + 16 * LDA * 2;

    if (NCH > 1) cp_wait<1>(); else cp_wait<0>();
    __syncthreads();   // chunk 0 visible (also covers sA producer writes)

    Frag f0, f1;
    load_frag(f0, aaddr0, aaddr1, ring, wn, lane);   // (c=0, kh=0)

#pragma unroll 1
    for (int c = 0; c < NCH; ++c) {
        const char* slot = ring + (c % 3) * 32768;
        // prep (c, kh=1) into f1, then HMMA f0
        load_frag(f1, aaddr0 + 32, aaddr1 + 32, slot + 16384, wn, lane);
        do_mma(acc, f0);
        // prep (c+1, kh=0) into f0 (barrier first), then HMMA f1
        if (c + 1 < NCH) {
            if (c + 2 < NCH) {
                load_super(Wg, ring, c + 2, tid);
                cp_wait<1>();
            } else {
                cp_wait<0>();
            }
            __syncthreads();   // chunk c+1 visible; slot of c-1 safely reusable
            load_frag(f0, aaddr0 + 64, aaddr1 + 64, ring + ((c + 1) % 3) * 32768,
                      wn, lane);
        }
        do_mma(acc, f1);
        aaddr0 += 64;   // 32 halves per super-chunk
        aaddr1 += 64;
    }
    __syncthreads();   // all frag reads of sA done before store_h overwrites it
}

__device__ __forceinline__ void store_h(const float acc[2][8][4], __half* sA,
                                        const float* sBias, int lane, int wm, int wn) {
    const int g = lane >> 2;
    const int t4 = lane & 3;
#pragma unroll
    for (int m = 0; m < 2; ++m) {
        const int row0 = wm * 32 + m * 16 + g;
#pragma unroll
        for (int n = 0; n < 8; ++n) {
            const int col = wn * 64 + n * 8 + 2 * t4;
            const float b0 = sBias[col], b1 = sBias[col + 1];
            *(uint32_t*)(sA + row0 * LDA + col) =
                pack_f16x2(fast_tanh(acc[m][n][0] + b0), fast_tanh(acc[m][n][1] + b1));
            *(uint32_t*)(sA + (row0 + 8) * LDA + col) =
                pack_f16x2(fast_tanh(acc[m][n][2] + b0), fast_tanh(acc[m][n][3] + b1));
        }
    }
}

__global__ __launch_bounds__(NTHREADS, 1)
void decoder_kernel(const float* __restrict__ x, const float* __restrict__ koop,
                    const float* __restrict__ sb1, const float* __restrict__ sb2,
                    const float* __restrict__ sb3,
                    const float* __restrict__ sW4, const float* __restrict__ sb4,
                    const float* __restrict__ tb1, const float* __restrict__ tb2,
                    const float* __restrict__ tb3,
                    const float* __restrict__ tW4, const float* __restrict__ tb4,
                    float* __restrict__ out) {
    extern __shared__ char smem[];
    __half* sA = (__half*)(smem + OFF_A);
    char* ring = smem + OFF_W;
    float* sBias = (float*)(smem + OFF_BIAS);
    float* sRed = (float*)(smem + OFF_RED);
    float* sS = (float*)(smem + OFF_S);

    const int tid = threadIdx.x;
    const int lane = tid & 31;
    const int wid = tid >> 5;
    const int wm = wid >> 3;   // 0..1
    const int wn = wid & 7;    // 0..7
    const int b = blockIdx.x;

    float acc[2][8][4];

#pragma unroll 1
    for (int mlp = 0; mlp < 2; ++mlp) {
        const uint32_t* W1 = g_wblob + c_blob_off[mlp * 3 + 0];
        const uint32_t* W2 = g_wblob + c_blob_off[mlp * 3 + 1];
        const uint32_t* W3 = g_wblob + c_blob_off[mlp * 3 + 2];
        const float* b1 = mlp ? tb1 : sb1;
        const float* b2 = mlp ? tb2 : sb2;
        const float* b3 = mlp ? tb3 : sb3;
        const float* W4 = mlp ? tW4 : sW4;
        const float* b4 = mlp ? tb4 : sb4;

        // z load: sA[d][l] = koopman[b, l, d] as f16
        const float* kb = koop + (size_t)b * 4096;
        for (int i = tid; i < 4096; i += NTHREADS) {
            const int l = i >> 6, d = i & 63;
            sA[d * LDA + l] = __float2half_rn(kb[i]);
        }
        // visibility: gemm_layer's first internal __syncthreads

        gemm_layer<2>(W1, b1, sA, ring, sBias, acc, tid, lane, wm, wn);
        store_h(acc, sA, sBias, lane, wm, wn);
        __syncthreads();
        gemm_layer<16>(W2, b2, sA, ring, sBias, acc, tid, lane, wm, wn);
        store_h(acc, sA, sBias, lane, wm, wn);
        __syncthreads();
        gemm_layer<16>(W3, b3, sA, ring, sBias, acc, tid, lane, wm, wn);
        store_h(acc, sA, sBias, lane, wm, wn);
        __syncthreads();

        // layer 4 diagonal: row r dots W4[:, r]; 8 partials per row
        const int r = tid & 63;
        const int p = tid >> 6;   // 0..7
        float a4 = 0.0f;
        const __half2* hrow = (const __half2*)(sA + r * LDA + p * 64);
        const float* wcol = W4 + (size_t)(p * 64) * 64 + r;
#pragma unroll 8
        for (int i = 0; i < 32; ++i) {
            const float2 hv = __half22float2(hrow[i]);
            a4 += hv.x * __ldg(wcol + (size_t)(2 * i) * 64);
            a4 += hv.y * __ldg(wcol + (size_t)(2 * i + 1) * 64);
        }
        sRed[p * 64 + r] = a4;
        __syncthreads();
        if (tid < 64) {
            float v = b4[tid];
#pragma unroll
            for (int p2 = 0; p2 < 8; ++p2) v += sRed[p2 * 64 + tid];
            if (mlp == 0) {
                sS[tid] = v;
            } else {
                const size_t o = (size_t)b * 64 + tid;
                out[o] = (x[o] - v) * __expf(-sS[tid]);
            }
        }
        __syncthreads();
    }
}

}  // namespace

extern "C" void kernel_launch(void* const* d_in, const int* in_sizes, int n_in,
                              void* d_out, int out_size) {
    (void)in_sizes; (void)n_in; (void)out_size;
    const float* x    = (const float*)d_in[0];
    const float* koop = (const float*)d_in[1];
    const float* sW1 = (const float*)d_in[2];  const float* sb1 = (const float*)d_in[3];
    const float* sW2 = (const float*)d_in[4];  const float* sb2 = (const float*)d_in[5];
    const float* sW3 = (const float*)d_in[6];  const float* sb3 = (const float*)d_in[7];
    const float* sW4 = (const float*)d_in[8];  const float* sb4 = (const float*)d_in[9];
    const float* tW1 = (const float*)d_in[10]; const float* tb1 = (const float*)d_in[11];
    const float* tW2 = (const float*)d_in[12]; const float* tb2 = (const float*)d_in[13];
    const float* tW3 = (const float*)d_in[14]; const float* tb3 = (const float*)d_in[15];
    const float* tW4 = (const float*)d_in[16]; const float* tb4 = (const float*)d_in[17];
    float* out = (float*)d_out;

    prep_kernel<<<(557056 + 255) / 256, 256>>>(sW1, sW2, sW3, tW1, tW2, tW3);

    cudaFuncSetAttribute(decoder_kernel, cudaFuncAttributeMaxDynamicSharedMemorySize,
                         SMEM_BYTES);
    decoder_kernel<<<2048, NTHREADS, SMEM_BYTES>>>(
        x, koop, sb1, sb2, sb3, sW4, sb4,
        tb1, tb2, tb3, tW4, tb4, out);
}

// round 9
// speedup vs baseline: 2.2261x; 1.1603x over previous
#include <cuda_runtime.h>
#include <cuda_fp16.h>
#include <cstdint>

// Decoder: out[b,d] = (x[b,d] - diag_t[b,d]) * exp(-diag_s[b,d])
// fp16 HMMA m16n8k16, one CTA per batch (M=64), 16 warps (2M x 8N).
// R8: B operands streamed straight from the fragment-major gmem blob via
// LDG.128 (L2-resident, zero SMEM staging, zero K-loop barriers); A via
// ldmatrix from SMEM. Register pipeline distance 2 on both operands.

namespace {

constexpr int Hn = 512;
constexpr int LDA = 520;        // A stride in halves (1040 B)
constexpr int NTHREADS = 512;   // 16 warps: 2(M) x 8(N)

// blob (u32 = f16x2), fragment-major in 16-k chunks: mlp0 L1,L2,L3 then mlp1
__device__ __align__(16) uint32_t g_wblob[557056];
__constant__ int c_blob_off[7] = {0, 16384, 147456, 278528, 294912, 425984, 557056};

// smem byte offsets
constexpr int OFF_A = 0;          // 66560 B : A tile 64 x LDA halves
constexpr int OFF_BIAS = 66560;   // 2048 B
constexpr int OFF_RED = 68608;    // 2048 B
constexpr int OFF_S = 70656;      // 256 B
constexpr int SMEM_BYTES = 70912;

__device__ __forceinline__ void mma16(float c[4], const unsigned a[4],
                                      unsigned b0, unsigned b1) {
    asm volatile(
        "mma.sync.aligned.m16n8k16.row.col.f32.f16.f16.f32 "
        "{%0,%1,%2,%3}, {%4,%5,%6,%7}, {%8,%9}, {%0,%1,%2,%3};"
        : "+f"(c[0]), "+f"(c[1]), "+f"(c[2]), "+f"(c[3])
        : "r"(a[0]), "r"(a[1]), "r"(a[2]), "r"(a[3]), "r"(b0), "r"(b1));
}
__device__ __forceinline__ void ldsm4(unsigned r[4], uint32_t addr) {
    asm volatile("ldmatrix.sync.aligned.m8n8.x4.shared.b16 {%0,%1,%2,%3}, [%4];"
                 : "=r"(r[0]), "=r"(r[1]), "=r"(r[2]), "=r"(r[3]) : "r"(addr));
}
__device__ __forceinline__ float fast_tanh(float x) {
    float e = __expf(2.0f * x);
    return 1.0f - __fdividef(2.0f, e + 1.0f);
}
__device__ __forceinline__ uint32_t pack_f16x2(float lo, float hi) {
    uint32_t r;
    asm("cvt.rn.f16x2.f32 %0, %1, %2;" : "=r"(r) : "f"(hi), "f"(lo));
    return r;
}

// ---- fused prep: all 6 hidden-layer weights -> fp16 fragment blob ----
// within a layer, u32 element e: q=e&3, lane=(e>>2)&31, p=(e>>7)&3, wn=(e>>9)&7,
// chunk=e>>12 (16-k chunks).
// k = chunk*16 + 2*(lane&3) + 8*(q&1);  col = wn*64 + (2p+(q>>1))*8 + (lane>>2)
__global__ void prep_kernel(const float* __restrict__ W0, const float* __restrict__ W1,
                            const float* __restrict__ W2, const float* __restrict__ W3,
                            const float* __restrict__ W4, const float* __restrict__ W5) {
    const int eg = blockIdx.x * blockDim.x + threadIdx.x;
    if (eg >= 557056) return;
    const float* srcs[6] = {W0, W1, W2, W3, W4, W5};
    int slot = 0;
    while (eg >= c_blob_off[slot + 1]) ++slot;
    const float* W = srcs[slot];
    const int e = eg - c_blob_off[slot];
    const int q = e & 3;
    const int lane = (e >> 2) & 31;
    const int p = (e >> 7) & 3;
    const int wn = (e >> 9) & 7;
    const int chunk = e >> 12;
    const int k = chunk * 16 + 2 * (lane & 3) + 8 * (q & 1);
    const int col = wn * 64 + (2 * p + (q >> 1)) * 8 + (lane >> 2);
    g_wblob[eg] = pack_f16x2(W[k * Hn + col], W[(k + 1) * Hn + col]);
}

// ---- main ----
__device__ __forceinline__ void do_mma(float acc[2][8][4], const unsigned a[2][4],
                                       const uint4 b[4]) {
#pragma unroll
    for (int p = 0; p < 4; ++p) {
        mma16(acc[0][2 * p],     a[0], b[p].x, b[p].y);
        mma16(acc[1][2 * p],     a[1], b[p].x, b[p].y);
        mma16(acc[0][2 * p + 1], a[0], b[p].z, b[p].w);
        mma16(acc[1][2 * p + 1], a[1], b[p].z, b[p].w);
    }
}

__device__ __forceinline__ void load_b(uint4 b[4], const uint4* __restrict__ bp) {
#pragma unroll
    for (int p = 0; p < 4; ++p) b[p] = __ldg(bp + p * 32);
}
__device__ __forceinline__ void load_a(unsigned a[2][4], uint32_t a0, uint32_t a1) {
    ldsm4(a[0], a0);
    ldsm4(a[1], a1);
}

// KH = K/16 kh-steps. B straight from gmem blob, A from SMEM via ldmatrix.
template <int KH>
__device__ __forceinline__ void gemm_layer(const uint4* __restrict__ Wg,
                                           const float* __restrict__ bias,
                                           __half* sA, float* sBias,
                                           float acc[2][8][4],
                                           int tid, int lane, int wm, int wn) {
#pragma unroll
    for (int m = 0; m < 2; ++m)
#pragma unroll
        for (int n = 0; n < 8; ++n)
#pragma unroll
            for (int q = 0; q < 4; ++q) acc[m][n][q] = 0.0f;

    sBias[tid] = bias[tid];

    const uint4* bp = Wg + wn * 128 + lane;   // +1024 uint4 per kh-step
    const int arow = wm * 32 + (lane & 15);
    const int acol = (lane >> 4) * 8;
    uint32_t aaddr0 = (unsigned)__cvta_generic_to_shared(sA + arow * LDA + acol);
    uint32_t aaddr1 = aaddr0 + 16 * LDA * 2;

    __syncthreads();   // sA producer writes (z-load / store_h) visible

    unsigned a[2][2][4];
    uint4 b[2][4];
    load_a(a[0], aaddr0, aaddr1);
    load_b(b[0], bp);
    load_a(a[1], aaddr0 + 32, aaddr1 + 32);
    load_b(b[1], bp + 1024);

#pragma unroll 2
    for (int kh = 0; kh < KH - 2; ++kh) {
        const int s = kh & 1;
        do_mma(acc, a[s], b[s]);
        load_a(a[s], aaddr0 + (kh + 2) * 32, aaddr1 + (kh + 2) * 32);
        load_b(b[s], bp + (size_t)(kh + 2) * 1024);
    }
    do_mma(acc, a[(KH - 2) & 1], b[(KH - 2) & 1]);
    do_mma(acc, a[(KH - 1) & 1], b[(KH - 1) & 1]);

    __syncthreads();   // all A reads done before store_h overwrites sA
}

__device__ __forceinline__ void store_h(const float acc[2][8][4], __half* sA,
                                        const float* sBias, int lane, int wm, int wn) {
    const int g = lane >> 2;
    const int t4 = lane & 3;
#pragma unroll
    for (int m = 0; m < 2; ++m) {
        const int row0 = wm * 32 + m * 16 + g;
#pragma unroll
        for (int n = 0; n < 8; ++n) {
            const int col = wn * 64 + n * 8 + 2 * t4;
            const float b0 = sBias[col], b1 = sBias[col + 1];
            *(uint32_t*)(sA + row0 * LDA + col) =
                pack_f16x2(fast_tanh(acc[m][n][0] + b0), fast_tanh(acc[m][n][1] + b1));
            *(uint32_t*)(sA + (row0 + 8) * LDA + col) =
                pack_f16x2(fast_tanh(acc[m][n][2] + b0), fast_tanh(acc[m][n][3] + b1));
        }
    }
}

__global__ __launch_bounds__(NTHREADS, 1)
void decoder_kernel(const float* __restrict__ x, const float* __restrict__ koop,
                    const float* __restrict__ sb1, const float* __restrict__ sb2,
                    const float* __restrict__ sb3,
                    const float* __restrict__ sW4, const float* __restrict__ sb4,
                    const float* __restrict__ tb1, const float* __restrict__ tb2,
                    const float* __restrict__ tb3,
                    const float* __restrict__ tW4, const float* __restrict__ tb4,
                    float* __restrict__ out) {
    extern __shared__ char smem[];
    __half* sA = (__half*)(smem + OFF_A);
    float* sBias = (float*)(smem + OFF_BIAS);
    float* sRed = (float*)(smem + OFF_RED);
    float* sS = (float*)(smem + OFF_S);

    const int tid = threadIdx.x;
    const int lane = tid & 31;
    const int wid = tid >> 5;
    const int wm = wid >> 3;   // 0..1
    const int wn = wid & 7;    // 0..7
    const int b = blockIdx.x;

    float acc[2][8][4];

#pragma unroll 1
    for (int mlp = 0; mlp < 2; ++mlp) {
        const uint4* W1 = (const uint4*)(g_wblob + c_blob_off[mlp * 3 + 0]);
        const uint4* W2 = (const uint4*)(g_wblob + c_blob_off[mlp * 3 + 1]);
        const uint4* W3 = (const uint4*)(g_wblob + c_blob_off[mlp * 3 + 2]);
        const float* b1 = mlp ? tb1 : sb1;
        const float* b2 = mlp ? tb2 : sb2;
        const float* b3 = mlp ? tb3 : sb3;
        const float* W4 = mlp ? tW4 : sW4;
        const float* b4 = mlp ? tb4 : sb4;

        // z load: sA[d][l] = koopman[b, l, d] as f16
        const float* kb = koop + (size_t)b * 4096;
        for (int i = tid; i < 4096; i += NTHREADS) {
            const int l = i >> 6, d = i & 63;
            sA[d * LDA + l] = __float2half_rn(kb[i]);
        }
        // visibility: gemm_layer's entry __syncthreads

        gemm_layer<4>(W1, b1, sA, sBias, acc, tid, lane, wm, wn);
        store_h(acc, sA, sBias, lane, wm, wn);
        __syncthreads();
        gemm_layer<32>(W2, b2, sA, sBias, acc, tid, lane, wm, wn);
        store_h(acc, sA, sBias, lane, wm, wn);
        __syncthreads();
        gemm_layer<32>(W3, b3, sA, sBias, acc, tid, lane, wm, wn);
        store_h(acc, sA, sBias, lane, wm, wn);
        __syncthreads();

        // layer 4 diagonal: row r dots W4[:, r]; 8 partials per row
        const int r = tid & 63;
        const int p = tid >> 6;   // 0..7
        float a4 = 0.0f;
        const __half2* hrow = (const __half2*)(sA + r * LDA + p * 64);
        const float* wcol = W4 + (size_t)(p * 64) * 64 + r;
#pragma unroll 8
        for (int i = 0; i < 32; ++i) {
            const float2 hv = __half22float2(hrow[i]);
            a4 += hv.x * __ldg(wcol + (size_t)(2 * i) * 64);
            a4 += hv.y * __ldg(wcol + (size_t)(2 * i + 1) * 64);
        }
        sRed[p * 64 + r] = a4;
        __syncthreads();
        if (tid < 64) {
            float v = b4[tid];
#pragma unroll
            for (int p2 = 0; p2 < 8; ++p2) v += sRed[p2 * 64 + tid];
            if (mlp == 0) {
                sS[tid] = v;
            } else {
                const size_t o = (size_t)b * 64 + tid;
                out[o] = (x[o] - v) * __expf(-sS[tid]);
            }
        }
        __syncthreads();
    }
}

}  // namespace

extern "C" void kernel_launch(void* const* d_in, const int* in_sizes, int n_in,
                              void* d_out, int out_size) {
    (void)in_sizes; (void)n_in; (void)out_size;
    const float* x    = (const float*)d_in[0];
    const float* koop = (const float*)d_in[1];
    const float* sW1 = (const float*)d_in[2];  const float* sb1 = (const float*)d_in[3];
    const float* sW2 = (const float*)d_in[4];  const float* sb2 = (const float*)d_in[5];
    const float* sW3 = (const float*)d_in[6];  const float* sb3 = (const float*)d_in[7];
    const float* sW4 = (const float*)d_in[8];  const float* sb4 = (const float*)d_in[9];
    const float* tW1 = (const float*)d_in[10]; const float* tb1 = (const float*)d_in[11];
    const float* tW2 = (const float*)d_in[12]; const float* tb2 = (const float*)d_in[13];
    const float* tW3 = (const float*)d_in[14]; const float* tb3 = (const float*)d_in[15];
    const float* tW4 = (const float*)d_in[16]; const float* tb4 = (const float*)d_in[17];
    float* out = (float*)d_out;

    prep_kernel<<<(557056 + 255) / 256, 256>>>(sW1, sW2, sW3, tW1, tW2, tW3);

    cudaFuncSetAttribute(decoder_kernel, cudaFuncAttributeMaxDynamicSharedMemorySize,
                         SMEM_BYTES);
    decoder_kernel<<<2048, NTHREADS, SMEM_BYTES>>>(
        x, koop, sb1, sb2, sb3, sW4, sb4,
        tb1, tb2, tb3, tW4, tb4, out);
}

// round 10
// speedup vs baseline: 2.2847x; 1.0263x over previous
#include <cuda_runtime.h>
#include <cuda_fp16.h>
#include <cstdint>

// Decoder: out[b,d] = (x[b,d] - diag_t[b,d]) * exp(-diag_s[b,d])
// R9: two warp-groups of 8 (s-MLP / t-MLP) run independently with group-scoped
// named barriers; epilogue of one group overlaps HMMA of the other.
// B via LDG.128 from fragment-major blob (L2), A via ldmatrix from group SMEM.

namespace {

constexpr int Hn = 512;
constexpr int LDA = 520;        // A stride in halves (1040 B)
constexpr int NTHREADS = 512;   // 2 groups x 8 warps (2M x 4N per half)

// blob (u32 = f16x2), fragment-major in 16-k chunks: mlp0 L1,L2,L3 then mlp1
__device__ __align__(16) uint32_t g_wblob[557056];
__constant__ int c_blob_off[7] = {0, 16384, 147456, 278528, 294912, 425984, 557056};

// per-group smem layout (bytes)
constexpr int OFF_STG  = 66560;    // 64 x 264 halves staging (33792 B)
constexpr int OFF_BIAS = 100352;   // 3 x 512 f32 (6144 B)
constexpr int OFF_RED  = 106496;   // 4 x 64 f32 (1024 B)
constexpr int OFF_S    = 107520;   // 64 f32 (256 B)
constexpr int GRP      = 107776;
constexpr int SMEM_BYTES = 2 * GRP;   // 215552

__device__ __forceinline__ void mma16(float c[4], const unsigned a[4],
                                      unsigned b0, unsigned b1) {
    asm volatile(
        "mma.sync.aligned.m16n8k16.row.col.f32.f16.f16.f32 "
        "{%0,%1,%2,%3}, {%4,%5,%6,%7}, {%8,%9}, {%0,%1,%2,%3};"
        : "+f"(c[0]), "+f"(c[1]), "+f"(c[2]), "+f"(c[3])
        : "r"(a[0]), "r"(a[1]), "r"(a[2]), "r"(a[3]), "r"(b0), "r"(b1));
}
__device__ __forceinline__ void ldsm4(unsigned r[4], uint32_t addr) {
    asm volatile("ldmatrix.sync.aligned.m8n8.x4.shared.b16 {%0,%1,%2,%3}, [%4];"
                 : "=r"(r[0]), "=r"(r[1]), "=r"(r[2]), "=r"(r[3]) : "r"(addr));
}
__device__ __forceinline__ void gbar(int id) {
    asm volatile("bar.sync %0, 256;" :: "r"(id) : "memory");
}
__device__ __forceinline__ float fast_tanh(float x) {
    float e = __expf(2.0f * x);
    return 1.0f - __fdividef(2.0f, e + 1.0f);
}
__device__ __forceinline__ uint32_t pack_f16x2(float lo, float hi) {
    uint32_t r;
    asm("cvt.rn.f16x2.f32 %0, %1, %2;" : "=r"(r) : "f"(hi), "f"(lo));
    return r;
}

// ---- fused prep: all 6 hidden-layer weights -> fp16 fragment blob ----
__global__ void prep_kernel(const float* __restrict__ W0, const float* __restrict__ W1,
                            const float* __restrict__ W2, const float* __restrict__ W3,
                            const float* __restrict__ W4, const float* __restrict__ W5) {
    const int eg = blockIdx.x * blockDim.x + threadIdx.x;
    if (eg >= 557056) return;
    const float* srcs[6] = {W0, W1, W2, W3, W4, W5};
    int slot = 0;
    while (eg >= c_blob_off[slot + 1]) ++slot;
    const float* W = srcs[slot];
    const int e = eg - c_blob_off[slot];
    const int q = e & 3;
    const int lane = (e >> 2) & 31;
    const int p = (e >> 7) & 3;
    const int wn = (e >> 9) & 7;
    const int chunk = e >> 12;
    const int k = chunk * 16 + 2 * (lane & 3) + 8 * (q & 1);
    const int col = wn * 64 + (2 * p + (q >> 1)) * 8 + (lane >> 2);
    g_wblob[eg] = pack_f16x2(W[k * Hn + col], W[(k + 1) * Hn + col]);
}

// ---- main ----
__device__ __forceinline__ void do_mma(float acc[2][8][4], const unsigned a[2][4],
                                       const uint4 b[4]) {
#pragma unroll
    for (int p = 0; p < 4; ++p) {
        mma16(acc[0][2 * p],     a[0], b[p].x, b[p].y);
        mma16(acc[1][2 * p],     a[1], b[p].x, b[p].y);
        mma16(acc[0][2 * p + 1], a[0], b[p].z, b[p].w);
        mma16(acc[1][2 * p + 1], a[1], b[p].z, b[p].w);
    }
}
__device__ __forceinline__ void load_b(uint4 b[4], const uint4* __restrict__ bp) {
#pragma unroll
    for (int p = 0; p < 4; ++p) b[p] = __ldg(bp + p * 32);
}
__device__ __forceinline__ void load_a(unsigned a[2][4], uint32_t a0, uint32_t a1) {
    ldsm4(a[0], a0);
    ldsm4(a[1], a1);
}

// one 256-col half of a layer; KH = K/16
template <int KH>
__device__ __forceinline__ void gemm_half(const uint4* __restrict__ Wg, int h,
                                          const __half* sA, float acc[2][8][4],
                                          int lane, int wm, int wnl) {
#pragma unroll
    for (int m = 0; m < 2; ++m)
#pragma unroll
        for (int n = 0; n < 8; ++n)
#pragma unroll
            for (int q = 0; q < 4; ++q) acc[m][n][q] = 0.0f;

    const uint4* bp = Wg + (h * 4 + wnl) * 128 + lane;
    const int arow = wm * 32 + (lane & 15);
    const int acol = (lane >> 4) * 8;
    uint32_t a0 = (unsigned)__cvta_generic_to_shared(sA + arow * LDA + acol);
    uint32_t a1 = a0 + 16 * LDA * 2;

    unsigned a[2][2][4];
    uint4 b[2][4];
    load_a(a[0], a0, a1);
    load_b(b[0], bp);
    load_a(a[1], a0 + 32, a1 + 32);
    load_b(b[1], bp + 1024);

#pragma unroll 2
    for (int kh = 0; kh < KH - 2; ++kh) {
        const int s = kh & 1;
        do_mma(acc, a[s], b[s]);
        load_a(a[s], a0 + (kh + 2) * 32, a1 + (kh + 2) * 32);
        load_b(b[s], bp + (size_t)(kh + 2) * 1024);
    }
    do_mma(acc, a[(KH - 2) & 1], b[(KH - 2) & 1]);
    do_mma(acc, a[(KH - 1) & 1], b[(KH - 1) & 1]);
}

// tanh(acc+bias) for half 0 -> staging (stride 264 halves)
__device__ __forceinline__ void store_stg(const float acc[2][8][4], char* stg,
                                          const float* lb, int lane, int wm, int wnl) {
    const int g8 = lane >> 2, t4 = lane & 3;
#pragma unroll
    for (int m = 0; m < 2; ++m) {
        const int row0 = wm * 32 + m * 16 + g8;
#pragma unroll
        for (int n = 0; n < 8; ++n) {
            const int col = wnl * 64 + n * 8 + 2 * t4;
            const float b0 = lb[col], b1 = lb[col + 1];
            *(uint32_t*)(stg + (row0 * 264 + col) * 2) =
                pack_f16x2(fast_tanh(acc[m][n][0] + b0), fast_tanh(acc[m][n][1] + b1));
            *(uint32_t*)(stg + ((row0 + 8) * 264 + col) * 2) =
                pack_f16x2(fast_tanh(acc[m][n][2] + b0), fast_tanh(acc[m][n][3] + b1));
        }
    }
}
// tanh(acc+bias) for half 1 -> sA cols 256..511
__device__ __forceinline__ void store_hi(const float acc[2][8][4], __half* sA,
                                         const float* lb, int lane, int wm, int wnl) {
    const int g8 = lane >> 2, t4 = lane & 3;
#pragma unroll
    for (int m = 0; m < 2; ++m) {
        const int row0 = wm * 32 + m * 16 + g8;
#pragma unroll
        for (int n = 0; n < 8; ++n) {
            const int col = 256 + wnl * 64 + n * 8 + 2 * t4;
            const float b0 = lb[col], b1 = lb[col + 1];
            *(uint32_t*)(sA + row0 * LDA + col) =
                pack_f16x2(fast_tanh(acc[m][n][0] + b0), fast_tanh(acc[m][n][1] + b1));
            *(uint32_t*)(sA + (row0 + 8) * LDA + col) =
                pack_f16x2(fast_tanh(acc[m][n][2] + b0), fast_tanh(acc[m][n][3] + b1));
        }
    }
}

template <int KH>
__device__ __forceinline__ void process_layer(const uint4* __restrict__ Wg,
                                              const float* lb, __half* sA, char* stg,
                                              float acc[2][8][4], int lane, int wm,
                                              int wnl, int gtid, int barid) {
    gemm_half<KH>(Wg, 0, sA, acc, lane, wm, wnl);
    store_stg(acc, stg, lb, lane, wm, wnl);
    gemm_half<KH>(Wg, 1, sA, acc, lane, wm, wnl);
    gbar(barid);   // all A reads done; stg writes visible
    store_hi(acc, sA, lb, lane, wm, wnl);
#pragma unroll
    for (int j = 0; j < 8; ++j) {   // copy stg -> sA cols 0..255
        const int f4 = gtid + j * 256;
        const int row = f4 >> 5, c = f4 & 31;
        *(uint4*)((char*)sA + row * 1040 + c * 16) =
            *(const uint4*)(stg + row * 528 + c * 16);
    }
    gbar(barid);   // sA ready for next layer
}

__global__ __launch_bounds__(NTHREADS, 1)
void decoder_kernel(const float* __restrict__ x, const float* __restrict__ koop,
                    const float* __restrict__ sb1, const float* __restrict__ sb2,
                    const float* __restrict__ sb3,
                    const float* __restrict__ sW4, const float* __restrict__ sb4,
                    const float* __restrict__ tb1, const float* __restrict__ tb2,
                    const float* __restrict__ tb3,
                    const float* __restrict__ tW4, const float* __restrict__ tb4,
                    float* __restrict__ out) {
    extern __shared__ char smem[];
    const int tid = threadIdx.x, lane = tid & 31, wid = tid >> 5;
    const int grp = wid >> 3, gwid = wid & 7, gtid = tid & 255;
    const int wm = gwid >> 2, wnl = gwid & 3;
    const int barid = 1 + grp;
    char* gb = smem + grp * GRP;
    __half* sA = (__half*)gb;
    char* stg = gb + OFF_STG;
    float* sBias = (float*)(gb + OFF_BIAS);
    float* sRed = (float*)(gb + OFF_RED);
    float* sSg = (float*)(gb + OFF_S);
    const int b = blockIdx.x;

    const float* bias1 = grp ? tb1 : sb1;
    const float* bias2 = grp ? tb2 : sb2;
    const float* bias3 = grp ? tb3 : sb3;
    const float* W4 = grp ? tW4 : sW4;
    const float* b4 = grp ? tb4 : sb4;
    const uint4* W1 = (const uint4*)(g_wblob + c_blob_off[grp * 3 + 0]);
    const uint4* W2 = (const uint4*)(g_wblob + c_blob_off[grp * 3 + 1]);
    const uint4* W3 = (const uint4*)(g_wblob + c_blob_off[grp * 3 + 2]);

    // z load (group-private copy) + all biases
    const float* kb = koop + (size_t)b * 4096;
    for (int i = gtid; i < 4096; i += 256) {
        const int l = i >> 6, d = i & 63;
        sA[d * LDA + l] = __float2half_rn(kb[i]);
    }
    for (int i = gtid; i < 512; i += 256) {
        sBias[i] = __ldg(bias1 + i);
        sBias[512 + i] = __ldg(bias2 + i);
        sBias[1024 + i] = __ldg(bias3 + i);
    }
    gbar(barid);

    float acc[2][8][4];
    process_layer<4>(W1, sBias, sA, stg, acc, lane, wm, wnl, gtid, barid);
    process_layer<32>(W2, sBias + 512, sA, stg, acc, lane, wm, wnl, gtid, barid);
    process_layer<32>(W3, sBias + 1024, sA, stg, acc, lane, wm, wnl, gtid, barid);

    // layer 4 diagonal: row r dots W4[:, r]; 4 partials per row
    {
        const int r = gtid & 63, p = gtid >> 6;   // p in 0..3
        float a4 = 0.0f;
        const __half2* hrow = (const __half2*)(sA + r * LDA + p * 128);
        const float* wcol = W4 + (size_t)(p * 128) * 64 + r;
#pragma unroll 8
        for (int i = 0; i < 64; ++i) {
            const float2 hv = __half22float2(hrow[i]);
            a4 += hv.x * __ldg(wcol + (size_t)(2 * i) * 64);
            a4 += hv.y * __ldg(wcol + (size_t)(2 * i + 1) * 64);
        }
        sRed[p * 64 + r] = a4;
        gbar(barid);
        if (gtid < 64)
            sSg[gtid] = sRed[gtid] + sRed[64 + gtid] + sRed[128 + gtid]
                      + sRed[192 + gtid] + __ldg(b4 + gtid);
    }

    __syncthreads();   // cross-group: both diags ready
    if (tid < 64) {
        const float vs = *(const float*)(smem + OFF_S + tid * 4);
        const float vt = *(const float*)(smem + GRP + OFF_S + tid * 4);
        const size_t o = (size_t)b * 64 + tid;
        out[o] = (x[o] - vt) * __expf(-vs);
    }
}

}  // namespace

extern "C" void kernel_launch(void* const* d_in, const int* in_sizes, int n_in,
                              void* d_out, int out_size) {
    (void)in_sizes; (void)n_in; (void)out_size;
    const float* x    = (const float*)d_in[0];
    const float* koop = (const float*)d_in[1];
    const float* sW1 = (const float*)d_in[2];  const float* sb1 = (const float*)d_in[3];
    const float* sW2 = (const float*)d_in[4];  const float* sb2 = (const float*)d_in[5];
    const float* sW3 = (const float*)d_in[6];  const float* sb3 = (const float*)d_in[7];
    const float* sW4 = (const float*)d_in[8];  const float* sb4 = (const float*)d_in[9];
    const float* tW1 = (const float*)d_in[10]; const float* tb1 = (const float*)d_in[11];
    const float* tW2 = (const float*)d_in[12]; const float* tb2 = (const float*)d_in[13];
    const float* tW3 = (const float*)d_in[14]; const float* tb3 = (const float*)d_in[15];
    const float* tW4 = (const float*)d_in[16]; const float* tb4 = (const float*)d_in[17];
    float* out = (float*)d_out;

    prep_kernel<<<(557056 + 255) / 256, 256>>>(sW1, sW2, sW3, tW1, tW2, tW3);

    cudaFuncSetAttribute(decoder_kernel, cudaFuncAttributeMaxDynamicSharedMemorySize,
                         SMEM_BYTES);
    decoder_kernel<<<2048, NTHREADS, SMEM_BYTES>>>(
        x, koop, sb1, sb2, sb3, sW4, sb4,
        tb1, tb2, tb3, tW4, tb4, out);
}